// round 5
// baseline (speedup 1.0000x reference)
#include <cuda_runtime.h>
#include <cuda_bf16.h>
#include <math.h>
#include <cstdint>

#define MTOT 8192      // B*T
#define CDIM 2048      // H*D
#define T_LEN 4096
#define H_N 16
#define D_N 128

typedef __nv_bfloat16 bf16;

// ====================== scratch (static device memory) ======================
__device__ float g_bufq[MTOT * CDIM];
__device__ float g_bufk[MTOT * CDIM];
__device__ float g_bufv[MTOT * CDIM];
__device__ float g_cq[MTOT * CDIM];
__device__ float g_ck[MTOT * CDIM];
__device__ float g_cv[MTOT * CDIM];
__device__ float g_gate[MTOT * CDIM];
__device__ float g_gog[MTOT * CDIM];
__device__ float g_fa[MTOT * D_N];
__device__ float g_ga[MTOT * D_N];
__device__ float g_beta[MTOT * H_N];
__device__ float g_ogated[MTOT * CDIM];
// scan partial outputs (one per row-quarter)
__device__ float g_op0[MTOT * CDIM];
__device__ float g_op1[MTOT * CDIM];
__device__ float g_op2[MTOT * CDIM];
__device__ float g_op3[MTOT * CDIM];
// bf16 hi/lo split operands
__device__ bf16 g_xh[MTOT * CDIM];
__device__ bf16 g_xl[MTOT * CDIM];
__device__ bf16 g_oh[MTOT * CDIM];
__device__ bf16 g_ol[MTOT * CDIM];
__device__ bf16 g_fah[MTOT * D_N];
__device__ bf16 g_fal[MTOT * D_N];
__device__ bf16 g_gah[MTOT * D_N];
__device__ bf16 g_gal[MTOT * D_N];
// transposed + split weights (row n = W[:,n], K contiguous)
__device__ bf16 g_WqTh[CDIM * CDIM];
__device__ bf16 g_WqTl[CDIM * CDIM];
__device__ bf16 g_WkTh[CDIM * CDIM];
__device__ bf16 g_WkTl[CDIM * CDIM];
__device__ bf16 g_WvTh[CDIM * CDIM];
__device__ bf16 g_WvTl[CDIM * CDIM];
__device__ bf16 g_WoTh[CDIM * CDIM];
__device__ bf16 g_WoTl[CDIM * CDIM];
__device__ bf16 g_WfaTh[D_N * CDIM];
__device__ bf16 g_WfaTl[D_N * CDIM];
__device__ bf16 g_WgaTh[D_N * CDIM];
__device__ bf16 g_WgaTl[D_N * CDIM];
__device__ bf16 g_WfbTh[CDIM * D_N];
__device__ bf16 g_WfbTl[CDIM * D_N];
__device__ bf16 g_WgbTh[CDIM * D_N];
__device__ bf16 g_WgbTl[CDIM * D_N];
__device__ bf16 g_WbTh[H_N * CDIM];
__device__ bf16 g_WbTl[H_N * CDIM];

// ====================== helpers ============================================
__device__ __forceinline__ uint32_t smem_u32(const void* p) {
  uint32_t a;
  asm("{ .reg .u64 t; cvta.to.shared.u64 t, %1; cvt.u32.u64 %0, t; }"
      : "=r"(a) : "l"(p));
  return a;
}
__device__ __forceinline__ void cp16(uint32_t dst, const void* src, bool valid) {
  int sz = valid ? 16 : 0;
  asm volatile("cp.async.cg.shared.global [%0], [%1], 16, %2;"
               :: "r"(dst), "l"(src), "r"(sz) : "memory");
}
__device__ __forceinline__ void ldsm4(uint32_t* r, uint32_t addr) {
  asm volatile("ldmatrix.sync.aligned.m8n8.x4.shared.b16 {%0,%1,%2,%3}, [%4];"
               : "=r"(r[0]), "=r"(r[1]), "=r"(r[2]), "=r"(r[3]) : "r"(addr));
}
__device__ __forceinline__ void mma16816(float* c, const uint32_t* a,
                                         const uint32_t* b) {
  asm volatile(
      "mma.sync.aligned.m16n8k16.row.col.f32.bf16.bf16.f32 "
      "{%0,%1,%2,%3},{%4,%5,%6,%7},{%8,%9},{%0,%1,%2,%3};"
      : "+f"(c[0]), "+f"(c[1]), "+f"(c[2]), "+f"(c[3])
      : "r"(a[0]), "r"(a[1]), "r"(a[2]), "r"(a[3]), "r"(b[0]), "r"(b[1]));
}
// packed fp32x2 (Blackwell base-ISA; NOT an "a"-gated feature)
typedef unsigned long long ull;
__device__ __forceinline__ ull pk2(float lo, float hi) {
  ull r;
  asm("mov.b64 %0, {%1, %2};" : "=l"(r) : "f"(lo), "f"(hi));
  return r;
}
__device__ __forceinline__ float2 upk2(ull v) {
  float2 f;
  asm("mov.b64 {%0, %1}, %2;" : "=f"(f.x), "=f"(f.y) : "l"(v));
  return f;
}
__device__ __forceinline__ ull fma2(ull a, ull b, ull c) {
  ull r;
  asm("fma.rn.f32x2 %0, %1, %2, %3;" : "=l"(r) : "l"(a), "l"(b), "l"(c));
  return r;
}

// ====================== bf16 hi/lo split (contiguous) =======================
__global__ void split_kernel(const float* __restrict__ src,
                             bf16* __restrict__ h, bf16* __restrict__ l, int n) {
  int i = (blockIdx.x * blockDim.x + threadIdx.x) * 4;
  if (i >= n) return;
  float4 f = *(const float4*)&src[i];
  bf16 h0 = __float2bfloat16(f.x), h1 = __float2bfloat16(f.y);
  bf16 h2 = __float2bfloat16(f.z), h3 = __float2bfloat16(f.w);
  __nv_bfloat162 hh0 = {h0, h1}, hh1 = {h2, h3};
  __nv_bfloat162 ll0 = {__float2bfloat16(f.x - __bfloat162float(h0)),
                        __float2bfloat16(f.y - __bfloat162float(h1))};
  __nv_bfloat162 ll1 = {__float2bfloat16(f.z - __bfloat162float(h2)),
                        __float2bfloat16(f.w - __bfloat162float(h3))};
  *(__nv_bfloat162*)&h[i] = hh0; *(__nv_bfloat162*)&h[i + 2] = hh1;
  *(__nv_bfloat162*)&l[i] = ll0; *(__nv_bfloat162*)&l[i + 2] = ll1;
}

// ============== transpose + split: dst[c][r] = split(src[r][c]) =============
__global__ void transpose_split(const float* __restrict__ src,
                                bf16* __restrict__ dh, bf16* __restrict__ dl,
                                int rows, int cols) {
  __shared__ float t[32][33];
  int bx = blockIdx.x * 32, by = blockIdx.y * 32;
  int tx = threadIdx.x;
  for (int j = threadIdx.y; j < 32; j += 8) {
    int r = by + j, c = bx + tx;
    if (r < rows && c < cols) t[j][tx] = src[(size_t)r * cols + c];
  }
  __syncthreads();
  int ro = by + tx;
  for (int j = threadIdx.y; j < 32; j += 8) {
    int c = bx + j;
    if (c < cols && ro < rows) {
      float v = t[tx][j];
      bf16 h = __float2bfloat16(v);
      dh[(size_t)c * rows + ro] = h;
      dl[(size_t)c * rows + ro] = __float2bfloat16(v - __bfloat162float(h));
    }
  }
}

// ====================== bf16 mma.sync GEMM (3-term split) ===================
// C[M,N] = A[M,K]*Bt[N,K]^T using (AhBh + AhBl + AlBh).
// Tile 128x128, BK=32, 8 warps (2x4), warp tile 64x32. 3-stage cp.async
// pipeline, ONE barrier per chunk. smem rows padded to 80B (conflict-free).
#define TILE_B 10240          // one 128x32 bf16 tile (80B rows)
#define BUF_B  (4 * TILE_B)   // Ah, Al, Bh, Bl
#define STAGES 3
__global__ __launch_bounds__(256, 1) void gemm_bf16(
    const bf16* __restrict__ Ah, const bf16* __restrict__ Al,
    const bf16* __restrict__ Bh, const bf16* __restrict__ Bl,
    float* __restrict__ C, int M, int N, int K) {
  extern __shared__ char smraw[];
  uint32_t sb = (smem_u32(smraw) + 127) & ~127u;

  int t = threadIdx.x;
  int wid = t >> 5, l = t & 31;
  int wm = wid >> 2, wn = wid & 3;           // warp grid 2x4
  int bm = blockIdx.y * 128, bn = blockIdx.x * 128;
  int NC = K >> 5;

  // loader role
  int tile = t >> 6;            // 0 Ah, 1 Al, 2 Bh, 3 Bl
  int u = t & 63;
  const bf16* src = (tile == 0) ? Ah : (tile == 1) ? Al : (tile == 2) ? Bh : Bl;
  int row0 = (tile < 2) ? bm : bn;
  bool isB = tile >= 2;

  auto issue = [&](int c) {
    uint32_t dbase = sb + (c % STAGES) * BUF_B + tile * TILE_B;
    int k0 = c << 5;
#pragma unroll
    for (int i = 0; i < 8; i++) {
      int idx = u * 8 + i;            // 0..511
      int r = idx >> 2, ch = idx & 3;
      int grow = row0 + r;
      bool valid = !isB || (grow < N);
      const bf16* sp = valid ? (src + (size_t)grow * K + k0 + ch * 8)
                             : (src);
      cp16(dbase + r * 80 + ch * 16, sp, valid);
    }
    asm volatile("cp.async.commit_group;" ::: "memory");
  };

  float acc[4][4][4];
#pragma unroll
  for (int a = 0; a < 4; a++)
#pragma unroll
    for (int b = 0; b < 4; b++)
#pragma unroll
      for (int d = 0; d < 4; d++) acc[a][b][d] = 0.f;

  int grp = l >> 3, r8 = l & 7;
  int aRow = wm * 64 + (grp & 1) * 8 + r8;     // + mt*16
  int aCol = (grp >> 1) * 16;                  // + ks*32
  int bRow = wn * 32 + (grp >> 1) * 8 + r8;    // + np*16
  int bCol = (grp & 1) * 16;                   // + ks*32

  issue(0);
  if (NC > 1) issue(1);
  for (int c = 0; c < NC; c++) {
    if (c == NC - 1)
      asm volatile("cp.async.wait_group 0;" ::: "memory");
    else
      asm volatile("cp.async.wait_group 1;" ::: "memory");
    __syncthreads();
    if (c + 2 < NC) issue(c + 2);   // buf (c+2)%3 == (c-1)%3, free after barrier

    uint32_t base = sb + (c % STAGES) * BUF_B;
#pragma unroll
    for (int ks = 0; ks < 2; ks++) {
      uint32_t ah[4][4], al[4][4], bh[4][2], bl[4][2];
#pragma unroll
      for (int mt = 0; mt < 4; mt++) {
        uint32_t ad = base + (aRow + mt * 16) * 80 + aCol + ks * 32;
        ldsm4(ah[mt], ad);
        ldsm4(al[mt], ad + TILE_B);
      }
#pragma unroll
      for (int np = 0; np < 2; np++) {
        uint32_t bd = base + 2 * TILE_B + (bRow + np * 16) * 80 + bCol + ks * 32;
        uint32_t rh[4], rl[4];
        ldsm4(rh, bd);
        ldsm4(rl, bd + TILE_B);
        bh[np * 2][0] = rh[0]; bh[np * 2][1] = rh[1];
        bh[np * 2 + 1][0] = rh[2]; bh[np * 2 + 1][1] = rh[3];
        bl[np * 2][0] = rl[0]; bl[np * 2][1] = rl[1];
        bl[np * 2 + 1][0] = rl[2]; bl[np * 2 + 1][1] = rl[3];
      }
#pragma unroll
      for (int mi = 0; mi < 4; mi++)
#pragma unroll
        for (int ni = 0; ni < 4; ni++) {
          mma16816(acc[mi][ni], ah[mi], bh[ni]);
          mma16816(acc[mi][ni], ah[mi], bl[ni]);
          mma16816(acc[mi][ni], al[mi], bh[ni]);
        }
    }
    __syncthreads();
  }

  // epilogue
  int rb = bm + wm * 64 + (l >> 2);
  int cb = bn + wn * 32 + 2 * (l & 3);
#pragma unroll
  for (int mi = 0; mi < 4; mi++) {
#pragma unroll
    for (int ni = 0; ni < 4; ni++) {
      int cc = cb + ni * 8;
      if (cc < N) {
        int r0 = rb + mi * 16;
        *(float2*)&C[(size_t)r0 * N + cc] =
            make_float2(acc[mi][ni][0], acc[mi][ni][1]);
        *(float2*)&C[(size_t)(r0 + 8) * N + cc] =
            make_float2(acc[mi][ni][2], acc[mi][ni][3]);
      }
    }
  }
}

// ========= fused: conv(K=4)+SiLU for q/k/v, l2norm q/k, gate, beta =========
// grid = MTOT*H_N blocks of 128 threads; block = one (bt, h)
__global__ __launch_bounds__(128) void conv_prep_kernel(
    const float* __restrict__ bq, const float* __restrict__ bk,
    const float* __restrict__ bv, const float* __restrict__ wq,
    const float* __restrict__ wk, const float* __restrict__ wv,
    const float* __restrict__ A_log, const float* __restrict__ dt_bias,
    float* __restrict__ cq, float* __restrict__ ck, float* __restrict__ cv,
    float* __restrict__ gate, float* __restrict__ beta) {
  int blk = blockIdx.x;  // bt*16 + h
  int h = blk & 15;
  int bt = blk >> 4;
  int d = threadIdx.x;   // 0..127
  int c = h * D_N + d;
  int t = bt & (T_LEN - 1);
  size_t idx = (size_t)bt * CDIM + c;

  float aq = 0.f, ak = 0.f, av = 0.f;
#pragma unroll
  for (int j = 0; j < 4; j++) {
    int ts = t + j - 3;
    if (ts >= 0) {
      size_t src = idx + (size_t)(j - 3) * CDIM;
      aq = fmaf(bq[src], wq[c * 4 + j], aq);
      ak = fmaf(bk[src], wk[c * 4 + j], ak);
      av = fmaf(bv[src], wv[c * 4 + j], av);
    }
  }
  aq = aq / (1.f + __expf(-aq));   // silu
  ak = ak / (1.f + __expf(-ak));
  av = av / (1.f + __expf(-av));

  // block-wide l2 norms of q,k
  float sq = aq * aq, sk = ak * ak;
#pragma unroll
  for (int o = 16; o > 0; o >>= 1) {
    sq += __shfl_xor_sync(0xffffffffu, sq, o);
    sk += __shfl_xor_sync(0xffffffffu, sk, o);
  }
  __shared__ float rq_[4], rk_[4];
  int wid = d >> 5, lane = d & 31;
  if (lane == 0) { rq_[wid] = sq; rk_[wid] = sk; }
  __syncthreads();
  float tq = rq_[0] + rq_[1] + rq_[2] + rq_[3];
  float tk = rk_[0] + rk_[1] + rk_[2] + rk_[3];

  cq[idx] = aq * rsqrtf(tq + 1e-6f) * 0.08838834764831845f;  // * D^-0.5
  ck[idx] = ak * rsqrtf(tk + 1e-6f);
  cv[idx] = av;

  float gp = gate[idx] + dt_bias[c];
  float sp = (gp > 0.f) ? gp + log1pf(__expf(-gp)) : log1pf(__expf(gp));
  gate[idx] = -__expf(A_log[h]) * sp;

  if (d == 0) {
    float bp = beta[(size_t)bt * H_N + h];
    beta[(size_t)bt * H_N + h] = 1.f / (1.f + __expf(-bp));
  }
}

// ====================== sequential gated delta-rule scan ====================
// 128 blocks = 32 (b,h) x 4 column groups; 128 threads. Thread (rq, cl) owns
// S[rows rq*32..+31][col j], packed as 16 f32x2. Double-buffered stage smem,
// 2 barriers/iter. Per-quarter o partials go straight to global (summed later).
__global__ __launch_bounds__(128) void kda_scan_kernel(
    const float* __restrict__ q, const float* __restrict__ k,
    const float* __restrict__ v, const float* __restrict__ g,
    const float* __restrict__ beta, float* __restrict__ op0,
    float* __restrict__ op1, float* __restrict__ op2,
    float* __restrict__ op3) {
  int bh = blockIdx.x >> 2;
  int cg = blockIdx.x & 3;
  int b = bh >> 4, h = bh & 15;
  int tid = threadIdx.x;
  int cl = tid & 31;
  int rq = tid >> 5;
  int j = cg * 32 + cl;
  int rbase = rq * 32;

  __shared__ float ks[2][128], qs[2][128], es[2][128];
  __shared__ float vs[2][32];
  __shared__ float kp[4][32];
  __shared__ float us[32];
  __shared__ float bsh[2];

  ull S2[16];
#pragma unroll
  for (int i = 0; i < 16; i++) S2[i] = 0ull;
  const ull ZERO2 = 0ull;   // packed (0.f, 0.f) bit pattern

  const size_t base = ((size_t)b * T_LEN) * CDIM + h * D_N;
  const size_t baseB = (size_t)b * T_LEN * H_N + h;
  float* __restrict__ opart = (rq == 0) ? op0 : (rq == 1) ? op1
                            : (rq == 2) ? op2 : op3;

  // t = 0: load + publish into buf 0
  float kr = k[base + tid];
  float qr = q[base + tid];
  float gr = g[base + tid];
  float vr = (tid < 32) ? v[base + j] : 0.f;
  float br = (tid == 0) ? beta[baseB] : 0.f;
  ks[0][tid] = kr; qs[0][tid] = qr; es[0][tid] = __expf(gr);
  if (tid < 32) vs[0][cl] = vr;
  if (tid == 0) bsh[0] = br;
  __syncthreads();

  for (int t = 0; t < T_LEN; t++) {
    int p = t & 1, pn = p ^ 1;
    // prefetch t+1 (latency hidden under pass1 + barrier)
    if (t + 1 < T_LEN) {
      size_t off2 = base + (size_t)(t + 1) * CDIM;
      kr = k[off2 + tid];
      qr = q[off2 + tid];
      gr = g[off2 + tid];
      if (tid < 32) vr = v[off2 + j];
      if (tid == 0) br = beta[baseB + (size_t)(t + 1) * H_N];
    }

    // pass 1: decay + k.S  (packed f32x2, 2 accumulator chains)
    ull kda = ZERO2, kdb = ZERO2;
#pragma unroll
    for (int i = 0; i < 16; i += 2) {
      ull E0 = *(const ull*)&es[p][rbase + 2 * i];
      ull K0 = *(const ull*)&ks[p][rbase + 2 * i];
      ull E1 = *(const ull*)&es[p][rbase + 2 * i + 2];
      ull K1 = *(const ull*)&ks[p][rbase + 2 * i + 2];
      S2[i]     = fma2(S2[i], E0, ZERO2);
      kda       = fma2(K0, S2[i], kda);
      S2[i + 1] = fma2(S2[i + 1], E1, ZERO2);
      kdb       = fma2(K1, S2[i + 1], kdb);
    }
    float2 ka = upk2(kda), kb = upk2(kdb);
    kp[rq][cl] = (ka.x + ka.y) + (kb.x + kb.y);
    __syncthreads();                       // barrier 1

    // publish t+1 into buf pn (safe: all pass2(t-1) readers done)
    if (t + 1 < T_LEN) {
      ks[pn][tid] = kr; qs[pn][tid] = qr; es[pn][tid] = __expf(gr);
      if (tid < 32) vs[pn][cl] = vr;
      if (tid == 0) bsh[pn] = br;
    }
    if (tid < 32)
      us[tid] = (vs[p][tid] -
                 (kp[0][tid] + kp[1][tid] + kp[2][tid] + kp[3][tid])) * bsh[p];
    __syncthreads();                       // barrier 2

    // pass 2: rank-1 update + q.S
    float u = us[cl];
    ull U2 = pk2(u, u);
    ull oda = ZERO2, odb = ZERO2;
#pragma unroll
    for (int i = 0; i < 16; i += 2) {
      ull K0 = *(const ull*)&ks[p][rbase + 2 * i];
      ull Q0 = *(const ull*)&qs[p][rbase + 2 * i];
      ull K1 = *(const ull*)&ks[p][rbase + 2 * i + 2];
      ull Q1 = *(const ull*)&qs[p][rbase + 2 * i + 2];
      S2[i]     = fma2(K0, U2, S2[i]);
      oda       = fma2(Q0, S2[i], oda);
      S2[i + 1] = fma2(K1, U2, S2[i + 1]);
      odb       = fma2(Q1, S2[i + 1], odb);
    }
    float2 oa = upk2(oda), ob = upk2(odb);
    opart[base + (size_t)t * CDIM + j] = (oa.x + oa.y) + (ob.x + ob.y);
  }
}

// ============ gated RMSNorm (sums the 4 scan partials inline) ==============
__global__ __launch_bounds__(128) void gatenorm_kernel(
    const float* __restrict__ op0, const float* __restrict__ op1,
    const float* __restrict__ op2, const float* __restrict__ op3,
    const float* __restrict__ go, const float* __restrict__ w,
    float* __restrict__ out) {
  int blk = blockIdx.x;   // bt*16 + h
  int d = threadIdx.x;
  size_t idx = (size_t)blk * D_N + d;
  float ov = (op0[idx] + op1[idx]) + (op2[idx] + op3[idx]);
  float s = ov * ov;
#pragma unroll
  for (int off = 16; off > 0; off >>= 1) s += __shfl_xor_sync(0xffffffffu, s, off);
  __shared__ float r_[4];
  int wid = d >> 5, lane = d & 31;
  if (lane == 0) r_[wid] = s;
  __syncthreads();
  float tot = r_[0] + r_[1] + r_[2] + r_[3];
  float rms = rsqrtf(tot * (1.f / 128.f) + 1e-6f);
  float gov = go[idx];
  out[idx] = ov * rms * w[d] * (1.f / (1.f + __expf(-gov)));
}

// ====================== launch =============================================
extern "C" void kernel_launch(void* const* d_in, const int* in_sizes, int n_in,
                              void* d_out, int out_size) {
  const float* x        = (const float*)d_in[0];
  const float* Wq       = (const float*)d_in[1];
  const float* Wk       = (const float*)d_in[2];
  const float* Wv       = (const float*)d_in[3];
  const float* conv_q_w = (const float*)d_in[4];
  const float* conv_k_w = (const float*)d_in[5];
  const float* conv_v_w = (const float*)d_in[6];
  const float* A_log    = (const float*)d_in[7];
  const float* Wfa      = (const float*)d_in[8];
  const float* Wfb      = (const float*)d_in[9];
  const float* dt_bias  = (const float*)d_in[10];
  const float* Wb       = (const float*)d_in[11];
  const float* Wga      = (const float*)d_in[12];
  const float* Wgb      = (const float*)d_in[13];
  const float* o_norm_w = (const float*)d_in[14];
  const float* Wo       = (const float*)d_in[15];
  float* out = (float*)d_out;

  float *bq, *bk, *bv, *cq, *ck, *cv, *gate, *gog, *fa, *ga, *beta, *ogated;
  float *op0, *op1, *op2, *op3;
  cudaGetSymbolAddress((void**)&bq, g_bufq);
  cudaGetSymbolAddress((void**)&bk, g_bufk);
  cudaGetSymbolAddress((void**)&bv, g_bufv);
  cudaGetSymbolAddress((void**)&cq, g_cq);
  cudaGetSymbolAddress((void**)&ck, g_ck);
  cudaGetSymbolAddress((void**)&cv, g_cv);
  cudaGetSymbolAddress((void**)&gate, g_gate);
  cudaGetSymbolAddress((void**)&gog, g_gog);
  cudaGetSymbolAddress((void**)&fa, g_fa);
  cudaGetSymbolAddress((void**)&ga, g_ga);
  cudaGetSymbolAddress((void**)&beta, g_beta);
  cudaGetSymbolAddress((void**)&ogated, g_ogated);
  cudaGetSymbolAddress((void**)&op0, g_op0);
  cudaGetSymbolAddress((void**)&op1, g_op1);
  cudaGetSymbolAddress((void**)&op2, g_op2);
  cudaGetSymbolAddress((void**)&op3, g_op3);

  bf16 *xh, *xl, *oh, *ol, *fah, *fal, *gah, *gal;
  bf16 *WqTh, *WqTl, *WkTh, *WkTl, *WvTh, *WvTl, *WoTh, *WoTl;
  bf16 *WfaTh, *WfaTl, *WgaTh, *WgaTl, *WfbTh, *WfbTl, *WgbTh, *WgbTl;
  bf16 *WbTh, *WbTl;
  cudaGetSymbolAddress((void**)&xh, g_xh);
  cudaGetSymbolAddress((void**)&xl, g_xl);
  cudaGetSymbolAddress((void**)&oh, g_oh);
  cudaGetSymbolAddress((void**)&ol, g_ol);
  cudaGetSymbolAddress((void**)&fah, g_fah);
  cudaGetSymbolAddress((void**)&fal, g_fal);
  cudaGetSymbolAddress((void**)&gah, g_gah);
  cudaGetSymbolAddress((void**)&gal, g_gal);
  cudaGetSymbolAddress((void**)&WqTh, g_WqTh);
  cudaGetSymbolAddress((void**)&WqTl, g_WqTl);
  cudaGetSymbolAddress((void**)&WkTh, g_WkTh);
  cudaGetSymbolAddress((void**)&WkTl, g_WkTl);
  cudaGetSymbolAddress((void**)&WvTh, g_WvTh);
  cudaGetSymbolAddress((void**)&WvTl, g_WvTl);
  cudaGetSymbolAddress((void**)&WoTh, g_WoTh);
  cudaGetSymbolAddress((void**)&WoTl, g_WoTl);
  cudaGetSymbolAddress((void**)&WfaTh, g_WfaTh);
  cudaGetSymbolAddress((void**)&WfaTl, g_WfaTl);
  cudaGetSymbolAddress((void**)&WgaTh, g_WgaTh);
  cudaGetSymbolAddress((void**)&WgaTl, g_WgaTl);
  cudaGetSymbolAddress((void**)&WfbTh, g_WfbTh);
  cudaGetSymbolAddress((void**)&WfbTl, g_WfbTl);
  cudaGetSymbolAddress((void**)&WgbTh, g_WgbTh);
  cudaGetSymbolAddress((void**)&WgbTl, g_WgbTl);
  cudaGetSymbolAddress((void**)&WbTh, g_WbTh);
  cudaGetSymbolAddress((void**)&WbTl, g_WbTl);

  constexpr int GSMEM = STAGES * BUF_B + 256;   // 123136
  cudaFuncSetAttribute(gemm_bf16, cudaFuncAttributeMaxDynamicSharedMemorySize, GSMEM);

  dim3 tb(32, 8);
  transpose_split<<<dim3(64, 64), tb>>>(Wq, WqTh, WqTl, CDIM, CDIM);
  transpose_split<<<dim3(64, 64), tb>>>(Wk, WkTh, WkTl, CDIM, CDIM);
  transpose_split<<<dim3(64, 64), tb>>>(Wv, WvTh, WvTl, CDIM, CDIM);
  transpose_split<<<dim3(64, 64), tb>>>(Wo, WoTh, WoTl, CDIM, CDIM);
  transpose_split<<<dim3(4, 64), tb>>>(Wfa, WfaTh, WfaTl, CDIM, D_N);
  transpose_split<<<dim3(4, 64), tb>>>(Wga, WgaTh, WgaTl, CDIM, D_N);
  transpose_split<<<dim3(64, 4), tb>>>(Wfb, WfbTh, WfbTl, D_N, CDIM);
  transpose_split<<<dim3(64, 4), tb>>>(Wgb, WgbTh, WgbTl, D_N, CDIM);
  transpose_split<<<dim3(1, 64), tb>>>(Wb, WbTh, WbTl, CDIM, H_N);

  int nx = MTOT * CDIM;
  split_kernel<<<nx / 1024, 256>>>(x, xh, xl, nx);

  dim3 gBig(CDIM / 128, MTOT / 128);   // (16, 64)
  dim3 gN1(1, MTOT / 128);             // (1, 64)

  // projections (tensor cores via mma.sync)
  gemm_bf16<<<gBig, 256, GSMEM>>>(xh, xl, WqTh, WqTl, bq, MTOT, CDIM, CDIM);
  gemm_bf16<<<gBig, 256, GSMEM>>>(xh, xl, WkTh, WkTl, bk, MTOT, CDIM, CDIM);
  gemm_bf16<<<gBig, 256, GSMEM>>>(xh, xl, WvTh, WvTl, bv, MTOT, CDIM, CDIM);
  // low-rank gate paths
  gemm_bf16<<<gN1, 256, GSMEM>>>(xh, xl, WfaTh, WfaTl, fa, MTOT, D_N, CDIM);
  split_kernel<<<MTOT * D_N / 1024, 256>>>(fa, fah, fal, MTOT * D_N);
  gemm_bf16<<<gBig, 256, GSMEM>>>(fah, fal, WfbTh, WfbTl, gate, MTOT, CDIM, D_N);
  gemm_bf16<<<gN1, 256, GSMEM>>>(xh, xl, WgaTh, WgaTl, ga, MTOT, D_N, CDIM);
  split_kernel<<<MTOT * D_N / 1024, 256>>>(ga, gah, gal, MTOT * D_N);
  gemm_bf16<<<gBig, 256, GSMEM>>>(gah, gal, WgbTh, WgbTl, gog, MTOT, CDIM, D_N);
  // beta pre-activation (N=16, zfill + store guards)
  gemm_bf16<<<gN1, 256, GSMEM>>>(xh, xl, WbTh, WbTl, beta, MTOT, H_N, CDIM);

  // fused conv + silu + l2norm + gate + beta
  conv_prep_kernel<<<MTOT * H_N, 128>>>(bq, bk, bv, conv_q_w, conv_k_w,
                                        conv_v_w, A_log, dt_bias, cq, ck, cv,
                                        gate, beta);

  // sequential scan (partials per row-quarter)
  kda_scan_kernel<<<128, 128>>>(cq, ck, cv, gate, beta, op0, op1, op2, op3);

  // gated rmsnorm (sums partials)
  gatenorm_kernel<<<MTOT * H_N, 128>>>(op0, op1, op2, op3, gog, o_norm_w, ogated);

  // output projection
  split_kernel<<<nx / 1024, 256>>>(ogated, oh, ol, nx);
  gemm_bf16<<<gBig, 256, GSMEM>>>(oh, ol, WoTh, WoTl, out, MTOT, CDIM, CDIM);
}

// round 6
// speedup vs baseline: 1.1020x; 1.1020x over previous
#include <cuda_runtime.h>
#include <cuda_bf16.h>
#include <math.h>
#include <cstdint>

#define MTOT 8192      // B*T
#define CDIM 2048      // H*D
#define T_LEN 4096
#define H_N 16
#define D_N 128

typedef __nv_bfloat16 bf16;

// ====================== scratch (static device memory) ======================
__device__ float g_bufq[MTOT * CDIM];
__device__ float g_bufk[MTOT * CDIM];
__device__ float g_bufv[MTOT * CDIM];
__device__ float g_cq[MTOT * CDIM];
__device__ float g_ck[MTOT * CDIM];
__device__ float g_cv[MTOT * CDIM];
__device__ float g_gate[MTOT * CDIM];
__device__ float g_gog[MTOT * CDIM];
__device__ float g_fa[MTOT * D_N];
__device__ float g_ga[MTOT * D_N];
__device__ float g_beta[MTOT * H_N];
__device__ float g_oscan[MTOT * CDIM];
__device__ float g_ogated[MTOT * CDIM];
// bf16 hi/lo split operands
__device__ bf16 g_xh[MTOT * CDIM];
__device__ bf16 g_xl[MTOT * CDIM];
__device__ bf16 g_oh[MTOT * CDIM];
__device__ bf16 g_ol[MTOT * CDIM];
__device__ bf16 g_fah[MTOT * D_N];
__device__ bf16 g_fal[MTOT * D_N];
__device__ bf16 g_gah[MTOT * D_N];
__device__ bf16 g_gal[MTOT * D_N];
// transposed + split weights (row n = W[:,n], K contiguous)
__device__ bf16 g_WqTh[CDIM * CDIM];
__device__ bf16 g_WqTl[CDIM * CDIM];
__device__ bf16 g_WkTh[CDIM * CDIM];
__device__ bf16 g_WkTl[CDIM * CDIM];
__device__ bf16 g_WvTh[CDIM * CDIM];
__device__ bf16 g_WvTl[CDIM * CDIM];
__device__ bf16 g_WoTh[CDIM * CDIM];
__device__ bf16 g_WoTl[CDIM * CDIM];
__device__ bf16 g_WfaTh[D_N * CDIM];
__device__ bf16 g_WfaTl[D_N * CDIM];
__device__ bf16 g_WgaTh[D_N * CDIM];
__device__ bf16 g_WgaTl[D_N * CDIM];
__device__ bf16 g_WfbTh[CDIM * D_N];
__device__ bf16 g_WfbTl[CDIM * D_N];
__device__ bf16 g_WgbTh[CDIM * D_N];
__device__ bf16 g_WgbTl[CDIM * D_N];
__device__ bf16 g_WbTh[H_N * CDIM];
__device__ bf16 g_WbTl[H_N * CDIM];

// ====================== helpers ============================================
__device__ __forceinline__ uint32_t smem_u32(const void* p) {
  uint32_t a;
  asm("{ .reg .u64 t; cvta.to.shared.u64 t, %1; cvt.u32.u64 %0, t; }"
      : "=r"(a) : "l"(p));
  return a;
}
__device__ __forceinline__ void cp16(uint32_t dst, const void* src, bool valid) {
  int sz = valid ? 16 : 0;
  asm volatile("cp.async.cg.shared.global [%0], [%1], 16, %2;"
               :: "r"(dst), "l"(src), "r"(sz) : "memory");
}
__device__ __forceinline__ void ldsm4(uint32_t* r, uint32_t addr) {
  asm volatile("ldmatrix.sync.aligned.m8n8.x4.shared.b16 {%0,%1,%2,%3}, [%4];"
               : "=r"(r[0]), "=r"(r[1]), "=r"(r[2]), "=r"(r[3]) : "r"(addr));
}
__device__ __forceinline__ void mma16816(float* c, const uint32_t* a,
                                         const uint32_t* b) {
  asm volatile(
      "mma.sync.aligned.m16n8k16.row.col.f32.bf16.bf16.f32 "
      "{%0,%1,%2,%3},{%4,%5,%6,%7},{%8,%9},{%0,%1,%2,%3};"
      : "+f"(c[0]), "+f"(c[1]), "+f"(c[2]), "+f"(c[3])
      : "r"(a[0]), "r"(a[1]), "r"(a[2]), "r"(a[3]), "r"(b[0]), "r"(b[1]));
}

// ====================== bf16 hi/lo split (contiguous) =======================
__global__ void split_kernel(const float* __restrict__ src,
                             bf16* __restrict__ h, bf16* __restrict__ l, int n) {
  int i = (blockIdx.x * blockDim.x + threadIdx.x) * 4;
  if (i >= n) return;
  float4 f = *(const float4*)&src[i];
  bf16 h0 = __float2bfloat16(f.x), h1 = __float2bfloat16(f.y);
  bf16 h2 = __float2bfloat16(f.z), h3 = __float2bfloat16(f.w);
  __nv_bfloat162 hh0 = {h0, h1}, hh1 = {h2, h3};
  __nv_bfloat162 ll0 = {__float2bfloat16(f.x - __bfloat162float(h0)),
                        __float2bfloat16(f.y - __bfloat162float(h1))};
  __nv_bfloat162 ll1 = {__float2bfloat16(f.z - __bfloat162float(h2)),
                        __float2bfloat16(f.w - __bfloat162float(h3))};
  *(__nv_bfloat162*)&h[i] = hh0; *(__nv_bfloat162*)&h[i + 2] = hh1;
  *(__nv_bfloat162*)&l[i] = ll0; *(__nv_bfloat162*)&l[i + 2] = ll1;
}

// ============== transpose + split: dst[c][r] = split(src[r][c]) =============
__global__ void transpose_split(const float* __restrict__ src,
                                bf16* __restrict__ dh, bf16* __restrict__ dl,
                                int rows, int cols) {
  __shared__ float t[32][33];
  int bx = blockIdx.x * 32, by = blockIdx.y * 32;
  int tx = threadIdx.x;
  for (int j = threadIdx.y; j < 32; j += 8) {
    int r = by + j, c = bx + tx;
    if (r < rows && c < cols) t[j][tx] = src[(size_t)r * cols + c];
  }
  __syncthreads();
  int ro = by + tx;
  for (int j = threadIdx.y; j < 32; j += 8) {
    int c = bx + j;
    if (c < cols && ro < rows) {
      float v = t[tx][j];
      bf16 h = __float2bfloat16(v);
      dh[(size_t)c * rows + ro] = h;
      dl[(size_t)c * rows + ro] = __float2bfloat16(v - __bfloat162float(h));
    }
  }
}

// ====================== bf16 mma.sync GEMM (3-term split) ===================
// C[M,N] = A[M,K]*Bt[N,K]^T using (AhBh + AhBl + AlBh).
// Tile 128x128, BK=32, 8 warps (2x4), warp tile 64x32. Double-buffered smem.
// smem tile row padded to 80B -> conflict-free ldmatrix.  (round-4 version)
#define TILE_B 10240          // one 128x32 bf16 tile (80B rows)
#define BUF_B  (4 * TILE_B)   // Ah, Al, Bh, Bl
__global__ __launch_bounds__(256, 1) void gemm_bf16(
    const bf16* __restrict__ Ah, const bf16* __restrict__ Al,
    const bf16* __restrict__ Bh, const bf16* __restrict__ Bl,
    float* __restrict__ C, int M, int N, int K) {
  extern __shared__ char smraw[];
  uint32_t sb = (smem_u32(smraw) + 127) & ~127u;

  int t = threadIdx.x;
  int wid = t >> 5, l = t & 31;
  int wm = wid >> 2, wn = wid & 3;           // warp grid 2x4
  int bm = blockIdx.y * 128, bn = blockIdx.x * 128;
  int NC = K >> 5;

  // loader role
  int tile = t >> 6;            // 0 Ah, 1 Al, 2 Bh, 3 Bl
  int u = t & 63;
  const bf16* src = (tile == 0) ? Ah : (tile == 1) ? Al : (tile == 2) ? Bh : Bl;
  int row0 = (tile < 2) ? bm : bn;
  bool isB = tile >= 2;

  auto issue = [&](int c) {
    uint32_t dbase = sb + (c & 1) * BUF_B + tile * TILE_B;
    int k0 = c << 5;
#pragma unroll
    for (int i = 0; i < 8; i++) {
      int idx = u * 8 + i;            // 0..511
      int r = idx >> 2, ch = idx & 3;
      int grow = row0 + r;
      bool valid = !isB || (grow < N);
      const bf16* sp = valid ? (src + (size_t)grow * K + k0 + ch * 8)
                             : (src);
      cp16(dbase + r * 80 + ch * 16, sp, valid);
    }
    asm volatile("cp.async.commit_group;" ::: "memory");
  };

  float acc[4][4][4];
#pragma unroll
  for (int a = 0; a < 4; a++)
#pragma unroll
    for (int b = 0; b < 4; b++)
#pragma unroll
      for (int d = 0; d < 4; d++) acc[a][b][d] = 0.f;

  int grp = l >> 3, r8 = l & 7;
  int aRow = wm * 64 + (grp & 1) * 8 + r8;     // + mt*16
  int aCol = (grp >> 1) * 16;                  // + ks*32
  int bRow = wn * 32 + (grp >> 1) * 8 + r8;    // + np*16
  int bCol = (grp & 1) * 16;                   // + ks*32

  issue(0);
  for (int c = 0; c < NC; c++) {
    if (c + 1 < NC) {
      issue(c + 1);
      asm volatile("cp.async.wait_group 1;" ::: "memory");
    } else {
      asm volatile("cp.async.wait_group 0;" ::: "memory");
    }
    __syncthreads();

    uint32_t base = sb + (c & 1) * BUF_B;
#pragma unroll
    for (int ks = 0; ks < 2; ks++) {
      uint32_t ah[4][4], al[4][4], bh[4][2], bl[4][2];
#pragma unroll
      for (int mt = 0; mt < 4; mt++) {
        uint32_t ad = base + (aRow + mt * 16) * 80 + aCol + ks * 32;
        ldsm4(ah[mt], ad);
        ldsm4(al[mt], ad + TILE_B);
      }
#pragma unroll
      for (int np = 0; np < 2; np++) {
        uint32_t bd = base + 2 * TILE_B + (bRow + np * 16) * 80 + bCol + ks * 32;
        uint32_t rh[4], rl[4];
        ldsm4(rh, bd);
        ldsm4(rl, bd + TILE_B);
        bh[np * 2][0] = rh[0]; bh[np * 2][1] = rh[1];
        bh[np * 2 + 1][0] = rh[2]; bh[np * 2 + 1][1] = rh[3];
        bl[np * 2][0] = rl[0]; bl[np * 2][1] = rl[1];
        bl[np * 2 + 1][0] = rl[2]; bl[np * 2 + 1][1] = rl[3];
      }
#pragma unroll
      for (int mi = 0; mi < 4; mi++)
#pragma unroll
        for (int ni = 0; ni < 4; ni++) {
          mma16816(acc[mi][ni], ah[mi], bh[ni]);
          mma16816(acc[mi][ni], ah[mi], bl[ni]);
          mma16816(acc[mi][ni], al[mi], bh[ni]);
        }
    }
    __syncthreads();
  }

  // epilogue
  int rb = bm + wm * 64 + (l >> 2);
  int cb = bn + wn * 32 + 2 * (l & 3);
#pragma unroll
  for (int mi = 0; mi < 4; mi++) {
#pragma unroll
    for (int ni = 0; ni < 4; ni++) {
      int cc = cb + ni * 8;
      if (cc < N) {
        int r0 = rb + mi * 16;
        *(float2*)&C[(size_t)r0 * N + cc] =
            make_float2(acc[mi][ni][0], acc[mi][ni][1]);
        *(float2*)&C[(size_t)(r0 + 8) * N + cc] =
            make_float2(acc[mi][ni][2], acc[mi][ni][3]);
      }
    }
  }
}

// ========= fused: conv(K=4)+SiLU for q/k/v, l2norm q/k, gate, beta =========
// grid = MTOT*H_N blocks of 128 threads; block = one (bt, h)
__global__ __launch_bounds__(128) void conv_prep_kernel(
    const float* __restrict__ bq, const float* __restrict__ bk,
    const float* __restrict__ bv, const float* __restrict__ wq,
    const float* __restrict__ wk, const float* __restrict__ wv,
    const float* __restrict__ A_log, const float* __restrict__ dt_bias,
    float* __restrict__ cq, float* __restrict__ ck, float* __restrict__ cv,
    float* __restrict__ gate, float* __restrict__ beta) {
  int blk = blockIdx.x;  // bt*16 + h
  int h = blk & 15;
  int bt = blk >> 4;
  int d = threadIdx.x;   // 0..127
  int c = h * D_N + d;
  int t = bt & (T_LEN - 1);
  size_t idx = (size_t)bt * CDIM + c;

  float aq = 0.f, ak = 0.f, av = 0.f;
#pragma unroll
  for (int j = 0; j < 4; j++) {
    int ts = t + j - 3;
    if (ts >= 0) {
      size_t src = idx + (size_t)(j - 3) * CDIM;
      aq = fmaf(bq[src], wq[c * 4 + j], aq);
      ak = fmaf(bk[src], wk[c * 4 + j], ak);
      av = fmaf(bv[src], wv[c * 4 + j], av);
    }
  }
  aq = aq / (1.f + __expf(-aq));   // silu
  ak = ak / (1.f + __expf(-ak));
  av = av / (1.f + __expf(-av));

  // block-wide l2 norms of q,k
  float sq = aq * aq, sk = ak * ak;
#pragma unroll
  for (int o = 16; o > 0; o >>= 1) {
    sq += __shfl_xor_sync(0xffffffffu, sq, o);
    sk += __shfl_xor_sync(0xffffffffu, sk, o);
  }
  __shared__ float rq_[4], rk_[4];
  int wid = d >> 5, lane = d & 31;
  if (lane == 0) { rq_[wid] = sq; rk_[wid] = sk; }
  __syncthreads();
  float tq = rq_[0] + rq_[1] + rq_[2] + rq_[3];
  float tk = rk_[0] + rk_[1] + rk_[2] + rk_[3];

  cq[idx] = aq * rsqrtf(tq + 1e-6f) * 0.08838834764831845f;  // * D^-0.5
  ck[idx] = ak * rsqrtf(tk + 1e-6f);
  cv[idx] = av;

  float gp = gate[idx] + dt_bias[c];
  float sp = (gp > 0.f) ? gp + log1pf(__expf(-gp)) : log1pf(__expf(gp));
  gate[idx] = -__expf(A_log[h]) * sp;

  if (d == 0) {
    float bp = beta[(size_t)bt * H_N + h];
    beta[(size_t)bt * H_N + h] = 1.f / (1.f + __expf(-bp));
  }
}

// ====================== sequential gated delta-rule scan ====================
// (round-4 version, verbatim: known 7394us build)
__global__ __launch_bounds__(128) void kda_scan_kernel(
    const float* __restrict__ q, const float* __restrict__ k,
    const float* __restrict__ v, const float* __restrict__ g,
    const float* __restrict__ beta, float* __restrict__ o) {
  int bh = blockIdx.x >> 2;
  int cg = blockIdx.x & 3;
  int b = bh >> 4, h = bh & 15;
  int tid = threadIdx.x;
  int cl = tid & 31;
  int rq = tid >> 5;
  int j = cg * 32 + cl;
  int rbase = rq * 32;

  __shared__ float ks[128], qs[128], es[128];
  __shared__ float vs[32], us[32];
  __shared__ float kp[4][32], op[4][32];
  __shared__ float beta_sh;

  float S[32];
#pragma unroll
  for (int i = 0; i < 32; i++) S[i] = 0.f;

  const size_t base = ((size_t)b * T_LEN) * CDIM + h * D_N;
  const size_t baseB = (size_t)b * T_LEN * H_N + h;

  float kr = k[base + tid];
  float qr = q[base + tid];
  float gr = g[base + tid];
  float vr = (tid < 32) ? v[base + j] : 0.f;
  float br = (tid == 0) ? beta[baseB] : 0.f;

  for (int t = 0; t < T_LEN; t++) {
    ks[tid] = kr;
    qs[tid] = qr;
    es[tid] = __expf(gr);
    if (tid < 32) vs[cl] = vr;
    if (tid == 0) beta_sh = br;
    __syncthreads();

    if (t + 1 < T_LEN) {
      size_t off2 = base + (size_t)(t + 1) * CDIM;
      kr = k[off2 + tid];
      qr = q[off2 + tid];
      gr = g[off2 + tid];
      if (tid < 32) vr = v[off2 + j];
      if (tid == 0) br = beta[baseB + (size_t)(t + 1) * H_N];
    }

    float kd = 0.f;
#pragma unroll
    for (int i = 0; i < 32; i += 4) {
      float4 e4 = *(const float4*)&es[rbase + i];
      float4 k4 = *(const float4*)&ks[rbase + i];
      S[i + 0] *= e4.x; kd = fmaf(k4.x, S[i + 0], kd);
      S[i + 1] *= e4.y; kd = fmaf(k4.y, S[i + 1], kd);
      S[i + 2] *= e4.z; kd = fmaf(k4.z, S[i + 2], kd);
      S[i + 3] *= e4.w; kd = fmaf(k4.w, S[i + 3], kd);
    }
    kp[rq][cl] = kd;
    __syncthreads();

    if (tid < 32) {
      float u = (vs[tid] - (kp[0][tid] + kp[1][tid] + kp[2][tid] + kp[3][tid])) * beta_sh;
      us[tid] = u;
    }
    __syncthreads();

    float u = us[cl];
    float od = 0.f;
#pragma unroll
    for (int i = 0; i < 32; i += 4) {
      float4 k4 = *(const float4*)&ks[rbase + i];
      float4 q4 = *(const float4*)&qs[rbase + i];
      S[i + 0] = fmaf(k4.x, u, S[i + 0]); od = fmaf(q4.x, S[i + 0], od);
      S[i + 1] = fmaf(k4.y, u, S[i + 1]); od = fmaf(q4.y, S[i + 1], od);
      S[i + 2] = fmaf(k4.z, u, S[i + 2]); od = fmaf(q4.z, S[i + 2], od);
      S[i + 3] = fmaf(k4.w, u, S[i + 3]); od = fmaf(q4.w, S[i + 3], od);
    }
    op[rq][cl] = od;
    __syncthreads();

    if (tid < 32)
      o[base + (size_t)t * CDIM + j] =
          op[0][tid] + op[1][tid] + op[2][tid] + op[3][tid];
  }
}

// ====================== gated RMSNorm ======================================
__global__ void gatenorm_kernel(const float* __restrict__ o,
                                const float* __restrict__ go,
                                const float* __restrict__ w,
                                float* __restrict__ out) {
  int blk = blockIdx.x;   // bt*16 + h
  int d = threadIdx.x;
  int idx = blk * D_N + d;
  float ov = o[idx];
  float s = ov * ov;
#pragma unroll
  for (int off = 16; off > 0; off >>= 1) s += __shfl_xor_sync(0xffffffffu, s, off);
  __shared__ float r_[4];
  int wid = d >> 5, lane = d & 31;
  if (lane == 0) r_[wid] = s;
  __syncthreads();
  float tot = r_[0] + r_[1] + r_[2] + r_[3];
  float rms = rsqrtf(tot * (1.f / 128.f) + 1e-6f);
  float gov = go[idx];
  out[idx] = ov * rms * w[d] * (1.f / (1.f + __expf(-gov)));
}

// ====================== launch =============================================
extern "C" void kernel_launch(void* const* d_in, const int* in_sizes, int n_in,
                              void* d_out, int out_size) {
  const float* x        = (const float*)d_in[0];
  const float* Wq       = (const float*)d_in[1];
  const float* Wk       = (const float*)d_in[2];
  const float* Wv       = (const float*)d_in[3];
  const float* conv_q_w = (const float*)d_in[4];
  const float* conv_k_w = (const float*)d_in[5];
  const float* conv_v_w = (const float*)d_in[6];
  const float* A_log    = (const float*)d_in[7];
  const float* Wfa      = (const float*)d_in[8];
  const float* Wfb      = (const float*)d_in[9];
  const float* dt_bias  = (const float*)d_in[10];
  const float* Wb       = (const float*)d_in[11];
  const float* Wga      = (const float*)d_in[12];
  const float* Wgb      = (const float*)d_in[13];
  const float* o_norm_w = (const float*)d_in[14];
  const float* Wo       = (const float*)d_in[15];
  float* out = (float*)d_out;

  float *bq, *bk, *bv, *cq, *ck, *cv, *gate, *gog, *fa, *ga, *beta, *oscan, *ogated;
  cudaGetSymbolAddress((void**)&bq, g_bufq);
  cudaGetSymbolAddress((void**)&bk, g_bufk);
  cudaGetSymbolAddress((void**)&bv, g_bufv);
  cudaGetSymbolAddress((void**)&cq, g_cq);
  cudaGetSymbolAddress((void**)&ck, g_ck);
  cudaGetSymbolAddress((void**)&cv, g_cv);
  cudaGetSymbolAddress((void**)&gate, g_gate);
  cudaGetSymbolAddress((void**)&gog, g_gog);
  cudaGetSymbolAddress((void**)&fa, g_fa);
  cudaGetSymbolAddress((void**)&ga, g_ga);
  cudaGetSymbolAddress((void**)&beta, g_beta);
  cudaGetSymbolAddress((void**)&oscan, g_oscan);
  cudaGetSymbolAddress((void**)&ogated, g_ogated);

  bf16 *xh, *xl, *oh, *ol, *fah, *fal, *gah, *gal;
  bf16 *WqTh, *WqTl, *WkTh, *WkTl, *WvTh, *WvTl, *WoTh, *WoTl;
  bf16 *WfaTh, *WfaTl, *WgaTh, *WgaTl, *WfbTh, *WfbTl, *WgbTh, *WgbTl;
  bf16 *WbTh, *WbTl;
  cudaGetSymbolAddress((void**)&xh, g_xh);
  cudaGetSymbolAddress((void**)&xl, g_xl);
  cudaGetSymbolAddress((void**)&oh, g_oh);
  cudaGetSymbolAddress((void**)&ol, g_ol);
  cudaGetSymbolAddress((void**)&fah, g_fah);
  cudaGetSymbolAddress((void**)&fal, g_fal);
  cudaGetSymbolAddress((void**)&gah, g_gah);
  cudaGetSymbolAddress((void**)&gal, g_gal);
  cudaGetSymbolAddress((void**)&WqTh, g_WqTh);
  cudaGetSymbolAddress((void**)&WqTl, g_WqTl);
  cudaGetSymbolAddress((void**)&WkTh, g_WkTh);
  cudaGetSymbolAddress((void**)&WkTl, g_WkTl);
  cudaGetSymbolAddress((void**)&WvTh, g_WvTh);
  cudaGetSymbolAddress((void**)&WvTl, g_WvTl);
  cudaGetSymbolAddress((void**)&WoTh, g_WoTh);
  cudaGetSymbolAddress((void**)&WoTl, g_WoTl);
  cudaGetSymbolAddress((void**)&WfaTh, g_WfaTh);
  cudaGetSymbolAddress((void**)&WfaTl, g_WfaTl);
  cudaGetSymbolAddress((void**)&WgaTh, g_WgaTh);
  cudaGetSymbolAddress((void**)&WgaTl, g_WgaTl);
  cudaGetSymbolAddress((void**)&WfbTh, g_WfbTh);
  cudaGetSymbolAddress((void**)&WfbTl, g_WfbTl);
  cudaGetSymbolAddress((void**)&WgbTh, g_WgbTh);
  cudaGetSymbolAddress((void**)&WgbTl, g_WgbTl);
  cudaGetSymbolAddress((void**)&WbTh, g_WbTh);
  cudaGetSymbolAddress((void**)&WbTl, g_WbTl);

  constexpr int GSMEM = 2 * BUF_B + 256;   // 82176
  cudaFuncSetAttribute(gemm_bf16, cudaFuncAttributeMaxDynamicSharedMemorySize, GSMEM);

  dim3 tb(32, 8);
  // first 5 launches, so the 6th (profiled by ncu -s 5 -c 1) is gemm_bf16
  transpose_split<<<dim3(64, 64), tb>>>(Wq, WqTh, WqTl, CDIM, CDIM);
  transpose_split<<<dim3(64, 64), tb>>>(Wk, WkTh, WkTl, CDIM, CDIM);
  transpose_split<<<dim3(64, 64), tb>>>(Wv, WvTh, WvTl, CDIM, CDIM);
  transpose_split<<<dim3(64, 64), tb>>>(Wo, WoTh, WoTl, CDIM, CDIM);
  int nx = MTOT * CDIM;
  split_kernel<<<nx / 1024, 256>>>(x, xh, xl, nx);

  dim3 gBig(CDIM / 128, MTOT / 128);   // (16, 64)
  dim3 gN1(1, MTOT / 128);             // (1, 64)

  // projections (tensor cores via mma.sync) — q is launch #6 → profiled
  gemm_bf16<<<gBig, 256, GSMEM>>>(xh, xl, WqTh, WqTl, bq, MTOT, CDIM, CDIM);
  gemm_bf16<<<gBig, 256, GSMEM>>>(xh, xl, WkTh, WkTl, bk, MTOT, CDIM, CDIM);
  gemm_bf16<<<gBig, 256, GSMEM>>>(xh, xl, WvTh, WvTl, bv, MTOT, CDIM, CDIM);

  // remaining weight transposes
  transpose_split<<<dim3(4, 64), tb>>>(Wfa, WfaTh, WfaTl, CDIM, D_N);
  transpose_split<<<dim3(4, 64), tb>>>(Wga, WgaTh, WgaTl, CDIM, D_N);
  transpose_split<<<dim3(64, 4), tb>>>(Wfb, WfbTh, WfbTl, D_N, CDIM);
  transpose_split<<<dim3(64, 4), tb>>>(Wgb, WgbTh, WgbTl, D_N, CDIM);
  transpose_split<<<dim3(1, 64), tb>>>(Wb, WbTh, WbTl, CDIM, H_N);

  // low-rank gate paths
  gemm_bf16<<<gN1, 256, GSMEM>>>(xh, xl, WfaTh, WfaTl, fa, MTOT, D_N, CDIM);
  split_kernel<<<MTOT * D_N / 1024, 256>>>(fa, fah, fal, MTOT * D_N);
  gemm_bf16<<<gBig, 256, GSMEM>>>(fah, fal, WfbTh, WfbTl, gate, MTOT, CDIM, D_N);
  gemm_bf16<<<gN1, 256, GSMEM>>>(xh, xl, WgaTh, WgaTl, ga, MTOT, D_N, CDIM);
  split_kernel<<<MTOT * D_N / 1024, 256>>>(ga, gah, gal, MTOT * D_N);
  gemm_bf16<<<gBig, 256, GSMEM>>>(gah, gal, WgbTh, WgbTl, gog, MTOT, CDIM, D_N);
  // beta pre-activation (N=16, zfill + store guards)
  gemm_bf16<<<gN1, 256, GSMEM>>>(xh, xl, WbTh, WbTl, beta, MTOT, H_N, CDIM);

  // fused conv + silu + l2norm + gate + beta
  conv_prep_kernel<<<MTOT * H_N, 128>>>(bq, bk, bv, conv_q_w, conv_k_w,
                                        conv_v_w, A_log, dt_bias, cq, ck, cv,
                                        gate, beta);

  // sequential scan
  kda_scan_kernel<<<128, 128>>>(cq, ck, cv, gate, beta, oscan);

  // gated rmsnorm
  gatenorm_kernel<<<MTOT * H_N, 128>>>(oscan, gog, o_norm_w, ogated);

  // output projection
  split_kernel<<<nx / 1024, 256>>>(ogated, oh, ol, nx);
  gemm_bf16<<<gBig, 256, GSMEM>>>(oh, ol, WoTh, WoTl, out, MTOT, CDIM, CDIM);
}

// round 12
// speedup vs baseline: 1.4041x; 1.2741x over previous
#include <cuda_runtime.h>
#include <cuda_fp16.h>
#include <math.h>
#include <cstdint>

#define MTOT 8192      // B*T
#define CDIM 2048      // H*D
#define T_LEN 4096
#define H_N 16
#define D_N 128

typedef __half hf;

// ====================== scratch (static device memory) ======================
__device__ float g_bufq[MTOT * CDIM];
__device__ float g_bufk[MTOT * CDIM];
__device__ float g_bufv[MTOT * CDIM];
__device__ float g_cq[MTOT * CDIM];
__device__ float g_ck[MTOT * CDIM];
__device__ float g_cv[MTOT * CDIM];
__device__ float g_gate[MTOT * CDIM];
__device__ float g_gog[MTOT * CDIM];
__device__ float g_fa[MTOT * D_N];
__device__ float g_ga[MTOT * D_N];
__device__ float g_beta[MTOT * H_N];
__device__ float g_oscan[MTOT * CDIM];
// fp16 A-side operands
__device__ hf g_xh[MTOT * CDIM];
__device__ hf g_oh[MTOT * CDIM];
__device__ hf g_fah[MTOT * D_N];
__device__ hf g_gah[MTOT * D_N];
// transposed + split fp16 weights (row n = W[:,n], K contiguous)
__device__ hf g_WqTh[CDIM * CDIM];
__device__ hf g_WqTl[CDIM * CDIM];
__device__ hf g_WkTh[CDIM * CDIM];
__device__ hf g_WkTl[CDIM * CDIM];
__device__ hf g_WvTh[CDIM * CDIM];
__device__ hf g_WvTl[CDIM * CDIM];
__device__ hf g_WoTh[CDIM * CDIM];
__device__ hf g_WoTl[CDIM * CDIM];
__device__ hf g_WfaTh[D_N * CDIM];
__device__ hf g_WfaTl[D_N * CDIM];
__device__ hf g_WgaTh[D_N * CDIM];
__device__ hf g_WgaTl[D_N * CDIM];
__device__ hf g_WfbTh[CDIM * D_N];
__device__ hf g_WfbTl[CDIM * D_N];
__device__ hf g_WgbTh[CDIM * D_N];
__device__ hf g_WgbTl[CDIM * D_N];
__device__ hf g_WbTh[H_N * CDIM];
__device__ hf g_WbTl[H_N * CDIM];

// ====================== helpers ============================================
__device__ __forceinline__ uint32_t smem_u32(const void* p) {
  uint32_t a;
  asm("{ .reg .u64 t; cvta.to.shared.u64 t, %1; cvt.u32.u64 %0, t; }"
      : "=r"(a) : "l"(p));
  return a;
}
__device__ __forceinline__ void cp16(uint32_t dst, const void* src, bool valid) {
  int sz = valid ? 16 : 0;
  asm volatile("cp.async.cg.shared.global [%0], [%1], 16, %2;"
               :: "r"(dst), "l"(src), "r"(sz) : "memory");
}
__device__ __forceinline__ void ldsm4(uint32_t* r, uint32_t addr) {
  asm volatile("ldmatrix.sync.aligned.m8n8.x4.shared.b16 {%0,%1,%2,%3}, [%4];"
               : "=r"(r[0]), "=r"(r[1]), "=r"(r[2]), "=r"(r[3]) : "r"(addr));
}
__device__ __forceinline__ void mma16816(float* c, const uint32_t* a,
                                         const uint32_t* b) {
  asm volatile(
      "mma.sync.aligned.m16n8k16.row.col.f32.f16.f16.f32 "
      "{%0,%1,%2,%3},{%4,%5,%6,%7},{%8,%9},{%0,%1,%2,%3};"
      : "+f"(c[0]), "+f"(c[1]), "+f"(c[2]), "+f"(c[3])
      : "r"(a[0]), "r"(a[1]), "r"(a[2]), "r"(a[3]), "r"(b[0]), "r"(b[1]));
}

// ====================== fp32 -> fp16 convert (contiguous) ===================
__global__ void convert_kernel(const float* __restrict__ src,
                               hf* __restrict__ dst, int n) {
  int i = (blockIdx.x * blockDim.x + threadIdx.x) * 8;
  if (i >= n) return;
  float4 f0 = *(const float4*)&src[i];
  float4 f1 = *(const float4*)&src[i + 4];
  __half2 h[4];
  h[0] = __floats2half2_rn(f0.x, f0.y);
  h[1] = __floats2half2_rn(f0.z, f0.w);
  h[2] = __floats2half2_rn(f1.x, f1.y);
  h[3] = __floats2half2_rn(f1.z, f1.w);
  *(uint4*)&dst[i] = *(uint4*)h;
}

// ============== transpose + fp16 split: dst[c][r] = split(src[r][c]) ========
__global__ void transpose_split(const float* __restrict__ src,
                                hf* __restrict__ dh, hf* __restrict__ dl,
                                int rows, int cols) {
  __shared__ float t[32][33];
  int bx = blockIdx.x * 32, by = blockIdx.y * 32;
  int tx = threadIdx.x;
  for (int j = threadIdx.y; j < 32; j += 8) {
    int r = by + j, c = bx + tx;
    if (r < rows && c < cols) t[j][tx] = src[(size_t)r * cols + c];
  }
  __syncthreads();
  int ro = by + tx;
  for (int j = threadIdx.y; j < 32; j += 8) {
    int c = bx + j;
    if (c < cols && ro < rows) {
      float v = t[tx][j];
      hf h = __float2half_rn(v);
      dh[(size_t)c * rows + ro] = h;
      dl[(size_t)c * rows + ro] = __float2half_rn(v - __half2float(h));
    }
  }
}

// ====================== fp16 mma.sync GEMM (2-term B split) =================
// C[M,N] = A[M,K]*Bt[N,K]^T using Ah*(Bh + Bl)  (error ~2^-11 from A trunc).
// Tile 128x128, BK=32, 8 warps (2x4), warp tile 64x32. Double-buffered smem.
// smem tile rows padded to 80B -> conflict-free ldmatrix.
#define TILE_B 10240          // one 128x32 fp16 tile (80B rows)
#define BUF_B  (3 * TILE_B)   // Ah, Bh, Bl
__global__ __launch_bounds__(256, 1) void gemm_fp16(
    const hf* __restrict__ A, const hf* __restrict__ Bh,
    const hf* __restrict__ Bl, float* __restrict__ C, int M, int N, int K) {
  extern __shared__ char smraw[];
  uint32_t sb = (smem_u32(smraw) + 127) & ~127u;

  int t = threadIdx.x;
  int wid = t >> 5, l = t & 31;
  int wm = wid >> 2, wn = wid & 3;           // warp grid 2x4
  int bm = blockIdx.y * 128, bn = blockIdx.x * 128;
  int NC = K >> 5;

  // loader roles: threads 0-127 -> Ah (4 ops), 128-255 -> Bh (4 ops),
  // all 256 -> Bl (2 ops)
  int grpL = t >> 7;            // 0: A, 1: Bh
  int u = t & 127;
  const hf* src01 = grpL ? Bh : A;
  int row01 = grpL ? bn : bm;
  bool guard01 = (grpL != 0);

  auto issue = [&](int c) {
    uint32_t dbase = sb + (c & 1) * BUF_B;
    int k0 = c << 5;
#pragma unroll
    for (int i = 0; i < 4; i++) {
      int idx = u * 4 + i;            // 0..511
      int r = idx >> 2, ch = idx & 3;
      int grow = row01 + r;
      bool valid = !guard01 || (grow < N);
      const hf* sp = valid ? (src01 + (size_t)grow * K + k0 + ch * 8) : src01;
      cp16(dbase + grpL * TILE_B + r * 80 + ch * 16, sp, valid);
    }
#pragma unroll
    for (int i = 0; i < 2; i++) {
      int idx = t * 2 + i;            // 0..511
      int r = idx >> 2, ch = idx & 3;
      int grow = bn + r;
      bool valid = grow < N;
      const hf* sp = valid ? (Bl + (size_t)grow * K + k0 + ch * 8) : Bl;
      cp16(dbase + 2 * TILE_B + r * 80 + ch * 16, sp, valid);
    }
    asm volatile("cp.async.commit_group;" ::: "memory");
  };

  float acc[4][4][4];
#pragma unroll
  for (int a = 0; a < 4; a++)
#pragma unroll
    for (int b = 0; b < 4; b++)
#pragma unroll
      for (int d = 0; d < 4; d++) acc[a][b][d] = 0.f;

  int grp = l >> 3, r8 = l & 7;
  int aRow = wm * 64 + (grp & 1) * 8 + r8;     // + mt*16
  int aCol = (grp >> 1) * 16;                  // + ks*32
  int bRow = wn * 32 + (grp >> 1) * 8 + r8;    // + np*16
  int bCol = (grp & 1) * 16;                   // + ks*32

  issue(0);
  for (int c = 0; c < NC; c++) {
    if (c + 1 < NC) {
      issue(c + 1);
      asm volatile("cp.async.wait_group 1;" ::: "memory");
    } else {
      asm volatile("cp.async.wait_group 0;" ::: "memory");
    }
    __syncthreads();

    uint32_t base = sb + (c & 1) * BUF_B;
#pragma unroll
    for (int ks = 0; ks < 2; ks++) {
      uint32_t ah[4][4], bhf[4][2], blf[4][2];
#pragma unroll
      for (int mt = 0; mt < 4; mt++) {
        uint32_t ad = base + (aRow + mt * 16) * 80 + aCol + ks * 32;
        ldsm4(ah[mt], ad);
      }
#pragma unroll
      for (int np = 0; np < 2; np++) {
        uint32_t bd = base + TILE_B + (bRow + np * 16) * 80 + bCol + ks * 32;
        uint32_t rh[4], rl[4];
        ldsm4(rh, bd);
        ldsm4(rl, bd + TILE_B);
        bhf[np * 2][0] = rh[0]; bhf[np * 2][1] = rh[1];
        bhf[np * 2 + 1][0] = rh[2]; bhf[np * 2 + 1][1] = rh[3];
        blf[np * 2][0] = rl[0]; blf[np * 2][1] = rl[1];
        blf[np * 2 + 1][0] = rl[2]; blf[np * 2 + 1][1] = rl[3];
      }
#pragma unroll
      for (int mi = 0; mi < 4; mi++)
#pragma unroll
        for (int ni = 0; ni < 4; ni++) {
          mma16816(acc[mi][ni], ah[mi], bhf[ni]);
          mma16816(acc[mi][ni], ah[mi], blf[ni]);
        }
    }
    __syncthreads();
  }

  // epilogue
  int rb = bm + wm * 64 + (l >> 2);
  int cb = bn + wn * 32 + 2 * (l & 3);
#pragma unroll
  for (int mi = 0; mi < 4; mi++) {
#pragma unroll
    for (int ni = 0; ni < 4; ni++) {
      int cc = cb + ni * 8;
      if (cc < N) {
        int r0 = rb + mi * 16;
        *(float2*)&C[(size_t)r0 * N + cc] =
            make_float2(acc[mi][ni][0], acc[mi][ni][1]);
        *(float2*)&C[(size_t)(r0 + 8) * N + cc] =
            make_float2(acc[mi][ni][2], acc[mi][ni][3]);
      }
    }
  }
}

// ========= fused: conv(K=4)+SiLU for q/k/v, l2norm q/k, gate, beta =========
__global__ __launch_bounds__(128) void conv_prep_kernel(
    const float* __restrict__ bq, const float* __restrict__ bk,
    const float* __restrict__ bv, const float* __restrict__ wq,
    const float* __restrict__ wk, const float* __restrict__ wv,
    const float* __restrict__ A_log, const float* __restrict__ dt_bias,
    float* __restrict__ cq, float* __restrict__ ck, float* __restrict__ cv,
    float* __restrict__ gate, float* __restrict__ beta) {
  int blk = blockIdx.x;  // bt*16 + h
  int h = blk & 15;
  int bt = blk >> 4;
  int d = threadIdx.x;   // 0..127
  int c = h * D_N + d;
  int t = bt & (T_LEN - 1);
  size_t idx = (size_t)bt * CDIM + c;

  float aq = 0.f, ak = 0.f, av = 0.f;
#pragma unroll
  for (int j = 0; j < 4; j++) {
    int ts = t + j - 3;
    if (ts >= 0) {
      size_t src = idx + (size_t)(j - 3) * CDIM;
      aq = fmaf(bq[src], wq[c * 4 + j], aq);
      ak = fmaf(bk[src], wk[c * 4 + j], ak);
      av = fmaf(bv[src], wv[c * 4 + j], av);
    }
  }
  aq = aq / (1.f + __expf(-aq));   // silu
  ak = ak / (1.f + __expf(-ak));
  av = av / (1.f + __expf(-av));

  float sq = aq * aq, sk = ak * ak;
#pragma unroll
  for (int o = 16; o > 0; o >>= 1) {
    sq += __shfl_xor_sync(0xffffffffu, sq, o);
    sk += __shfl_xor_sync(0xffffffffu, sk, o);
  }
  __shared__ float rq_[4], rk_[4];
  int wid = d >> 5, lane = d & 31;
  if (lane == 0) { rq_[wid] = sq; rk_[wid] = sk; }
  __syncthreads();
  float tq = rq_[0] + rq_[1] + rq_[2] + rq_[3];
  float tk = rk_[0] + rk_[1] + rk_[2] + rk_[3];

  cq[idx] = aq * rsqrtf(tq + 1e-6f) * 0.08838834764831845f;
  ck[idx] = ak * rsqrtf(tk + 1e-6f);
  cv[idx] = av;

  float gp = gate[idx] + dt_bias[c];
  float sp = (gp > 0.f) ? gp + log1pf(__expf(-gp)) : log1pf(__expf(gp));
  gate[idx] = -__expf(A_log[h]) * sp;

  if (d == 0) {
    float bp = beta[(size_t)bt * H_N + h];
    beta[(size_t)bt * H_N + h] = 1.f / (1.f + __expf(-bp));
  }
}

// ====================== sequential gated delta-rule scan ====================
// 128 blocks = 32 (b,h) x 4 col groups; 256 threads: cl = tid&31 (col),
// rg = tid>>5 (0..7) owns rows rg*16..+15. S[16] regs/thread -> 16-FMA chains.
__global__ __launch_bounds__(256) void kda_scan_kernel(
    const float* __restrict__ q, const float* __restrict__ k,
    const float* __restrict__ v, const float* __restrict__ g,
    const float* __restrict__ beta, float* __restrict__ o) {
  int bh = blockIdx.x >> 2;
  int cg = blockIdx.x & 3;
  int b = bh >> 4, h = bh & 15;
  int tid = threadIdx.x;     // 0..255
  int cl = tid & 31;
  int rg = tid >> 5;         // 0..7
  int rbase = rg * 16;
  int t128 = tid & 127;
  bool loH = tid < 128;

  __shared__ float ks[128], qs[128], es[128];
  __shared__ float vs[32], us[32];
  __shared__ float kp[8][32], op[8][32];
  __shared__ float beta_sh;

  float S[16];
#pragma unroll
  for (int i = 0; i < 16; i++) S[i] = 0.f;

  const size_t base = ((size_t)b * T_LEN) * CDIM + h * D_N;
  const size_t baseB = (size_t)b * T_LEN * H_N + h;

  // role loads for t=0: lower half: k,g; upper half: q, v(first 32), beta
  float kr = 0.f, gr = 0.f, qr = 0.f, vr = 0.f, br = 0.f;
  if (loH) { kr = k[base + t128]; gr = g[base + t128]; }
  else {
    qr = q[base + t128];
    if (t128 < 32) vr = v[base + cg * 32 + t128];
    if (t128 == 0) br = beta[baseB];
  }

  for (int t = 0; t < T_LEN; t++) {
    // publish
    if (loH) { ks[t128] = kr; es[t128] = __expf(gr); }
    else {
      qs[t128] = qr;
      if (t128 < 32) vs[t128] = vr;
      if (t128 == 0) beta_sh = br;
    }
    __syncthreads();                       // B1

    // prefetch t+1
    if (t + 1 < T_LEN) {
      size_t off2 = base + (size_t)(t + 1) * CDIM;
      if (loH) { kr = k[off2 + t128]; gr = g[off2 + t128]; }
      else {
        qr = q[off2 + t128];
        if (t128 < 32) vr = v[off2 + cg * 32 + t128];
        if (t128 == 0) br = beta[baseB + (size_t)(t + 1) * H_N];
      }
    }

    // pass 1: decay + k.S (16-FMA chain)
    float kd = 0.f;
#pragma unroll
    for (int i = 0; i < 16; i += 4) {
      float4 e4 = *(const float4*)&es[rbase + i];
      float4 k4 = *(const float4*)&ks[rbase + i];
      S[i + 0] *= e4.x; kd = fmaf(k4.x, S[i + 0], kd);
      S[i + 1] *= e4.y; kd = fmaf(k4.y, S[i + 1], kd);
      S[i + 2] *= e4.z; kd = fmaf(k4.z, S[i + 2], kd);
      S[i + 3] *= e4.w; kd = fmaf(k4.w, S[i + 3], kd);
    }
    kp[rg][cl] = kd;
    __syncthreads();                       // B2

    if (tid < 32) {
      float s0 = (kp[0][tid] + kp[1][tid]) + (kp[2][tid] + kp[3][tid]);
      float s1 = (kp[4][tid] + kp[5][tid]) + (kp[6][tid] + kp[7][tid]);
      us[tid] = (vs[tid] - (s0 + s1)) * beta_sh;
    }
    __syncthreads();                       // B3

    // pass 2: rank-1 update + q.S
    float u = us[cl];
    float od = 0.f;
#pragma unroll
    for (int i = 0; i < 16; i += 4) {
      float4 k4 = *(const float4*)&ks[rbase + i];
      float4 q4 = *(const float4*)&qs[rbase + i];
      S[i + 0] = fmaf(k4.x, u, S[i + 0]); od = fmaf(q4.x, S[i + 0], od);
      S[i + 1] = fmaf(k4.y, u, S[i + 1]); od = fmaf(q4.y, S[i + 1], od);
      S[i + 2] = fmaf(k4.z, u, S[i + 2]); od = fmaf(q4.z, S[i + 2], od);
      S[i + 3] = fmaf(k4.w, u, S[i + 3]); od = fmaf(q4.w, S[i + 3], od);
    }
    op[rg][cl] = od;
    __syncthreads();                       // B4

    if (tid < 32) {
      float s0 = (op[0][tid] + op[1][tid]) + (op[2][tid] + op[3][tid]);
      float s1 = (op[4][tid] + op[5][tid]) + (op[6][tid] + op[7][tid]);
      o[base + (size_t)t * CDIM + cg * 32 + tid] = s0 + s1;
    }
  }
}

// ============ gated RMSNorm -> fp16 (feeds Wo GEMM directly) ===============
__global__ __launch_bounds__(128) void gatenorm_kernel(
    const float* __restrict__ o, const float* __restrict__ go,
    const float* __restrict__ w, hf* __restrict__ out) {
  int blk = blockIdx.x;   // bt*16 + h
  int d = threadIdx.x;
  size_t idx = (size_t)blk * D_N + d;
  float ov = o[idx];
  float s = ov * ov;
#pragma unroll
  for (int off = 16; off > 0; off >>= 1) s += __shfl_xor_sync(0xffffffffu, s, off);
  __shared__ float r_[4];
  int wid = d >> 5, lane = d & 31;
  if (lane == 0) r_[wid] = s;
  __syncthreads();
  float tot = r_[0] + r_[1] + r_[2] + r_[3];
  float rms = rsqrtf(tot * (1.f / 128.f) + 1e-6f);
  float gov = go[idx];
  out[idx] = __float2half_rn(ov * rms * w[d] * (1.f / (1.f + __expf(-gov))));
}

// ====================== launch =============================================
extern "C" void kernel_launch(void* const* d_in, const int* in_sizes, int n_in,
                              void* d_out, int out_size) {
  const float* x        = (const float*)d_in[0];
  const float* Wq       = (const float*)d_in[1];
  const float* Wk       = (const float*)d_in[2];
  const float* Wv       = (const float*)d_in[3];
  const float* conv_q_w = (const float*)d_in[4];
  const float* conv_k_w = (const float*)d_in[5];
  const float* conv_v_w = (const float*)d_in[6];
  const float* A_log    = (const float*)d_in[7];
  const float* Wfa      = (const float*)d_in[8];
  const float* Wfb      = (const float*)d_in[9];
  const float* dt_bias  = (const float*)d_in[10];
  const float* Wb       = (const float*)d_in[11];
  const float* Wga      = (const float*)d_in[12];
  const float* Wgb      = (const float*)d_in[13];
  const float* o_norm_w = (const float*)d_in[14];
  const float* Wo       = (const float*)d_in[15];
  float* out = (float*)d_out;

  float *bq, *bk, *bv, *cq, *ck, *cv, *gate, *gog, *fa, *ga, *beta, *oscan;
  cudaGetSymbolAddress((void**)&bq, g_bufq);
  cudaGetSymbolAddress((void**)&bk, g_bufk);
  cudaGetSymbolAddress((void**)&bv, g_bufv);
  cudaGetSymbolAddress((void**)&cq, g_cq);
  cudaGetSymbolAddress((void**)&ck, g_ck);
  cudaGetSymbolAddress((void**)&cv, g_cv);
  cudaGetSymbolAddress((void**)&gate, g_gate);
  cudaGetSymbolAddress((void**)&gog, g_gog);
  cudaGetSymbolAddress((void**)&fa, g_fa);
  cudaGetSymbolAddress((void**)&ga, g_ga);
  cudaGetSymbolAddress((void**)&beta, g_beta);
  cudaGetSymbolAddress((void**)&oscan, g_oscan);

  hf *xh, *oh, *fah, *gah;
  hf *WqTh, *WqTl, *WkTh, *WkTl, *WvTh, *WvTl, *WoTh, *WoTl;
  hf *WfaTh, *WfaTl, *WgaTh, *WgaTl, *WfbTh, *WfbTl, *WgbTh, *WgbTl;
  hf *WbTh, *WbTl;
  cudaGetSymbolAddress((void**)&xh, g_xh);
  cudaGetSymbolAddress((void**)&oh, g_oh);
  cudaGetSymbolAddress((void**)&fah, g_fah);
  cudaGetSymbolAddress((void**)&gah, g_gah);
  cudaGetSymbolAddress((void**)&WqTh, g_WqTh);
  cudaGetSymbolAddress((void**)&WqTl, g_WqTl);
  cudaGetSymbolAddress((void**)&WkTh, g_WkTh);
  cudaGetSymbolAddress((void**)&WkTl, g_WkTl);
  cudaGetSymbolAddress((void**)&WvTh, g_WvTh);
  cudaGetSymbolAddress((void**)&WvTl, g_WvTl);
  cudaGetSymbolAddress((void**)&WoTh, g_WoTh);
  cudaGetSymbolAddress((void**)&WoTl, g_WoTl);
  cudaGetSymbolAddress((void**)&WfaTh, g_WfaTh);
  cudaGetSymbolAddress((void**)&WfaTl, g_WfaTl);
  cudaGetSymbolAddress((void**)&WgaTh, g_WgaTh);
  cudaGetSymbolAddress((void**)&WgaTl, g_WgaTl);
  cudaGetSymbolAddress((void**)&WfbTh, g_WfbTh);
  cudaGetSymbolAddress((void**)&WfbTl, g_WfbTl);
  cudaGetSymbolAddress((void**)&WgbTh, g_WgbTh);
  cudaGetSymbolAddress((void**)&WgbTl, g_WgbTl);
  cudaGetSymbolAddress((void**)&WbTh, g_WbTh);
  cudaGetSymbolAddress((void**)&WbTl, g_WbTl);

  constexpr int GSMEM = 2 * BUF_B + 256;   // 61696
  cudaFuncSetAttribute(gemm_fp16, cudaFuncAttributeMaxDynamicSharedMemorySize, GSMEM);

  dim3 tb(32, 8);
  transpose_split<<<dim3(64, 64), tb>>>(Wq, WqTh, WqTl, CDIM, CDIM);
  transpose_split<<<dim3(64, 64), tb>>>(Wk, WkTh, WkTl, CDIM, CDIM);
  transpose_split<<<dim3(64, 64), tb>>>(Wv, WvTh, WvTl, CDIM, CDIM);
  transpose_split<<<dim3(64, 64), tb>>>(Wo, WoTh, WoTl, CDIM, CDIM);
  int nx = MTOT * CDIM;
  convert_kernel<<<nx / 2048, 256>>>(x, xh, nx);

  dim3 gBig(CDIM / 128, MTOT / 128);   // (16, 64)
  dim3 gN1(1, MTOT / 128);             // (1, 64)

  // projections
  gemm_fp16<<<gBig, 256, GSMEM>>>(xh, WqTh, WqTl, bq, MTOT, CDIM, CDIM);
  gemm_fp16<<<gBig, 256, GSMEM>>>(xh, WkTh, WkTl, bk, MTOT, CDIM, CDIM);
  gemm_fp16<<<gBig, 256, GSMEM>>>(xh, WvTh, WvTl, bv, MTOT, CDIM, CDIM);

  // remaining weight transposes
  transpose_split<<<dim3(4, 64), tb>>>(Wfa, WfaTh, WfaTl, CDIM, D_N);
  transpose_split<<<dim3(4, 64), tb>>>(Wga, WgaTh, WgaTl, CDIM, D_N);
  transpose_split<<<dim3(64, 4), tb>>>(Wfb, WfbTh, WfbTl, D_N, CDIM);
  transpose_split<<<dim3(64, 4), tb>>>(Wgb, WgbTh, WgbTl, D_N, CDIM);
  transpose_split<<<dim3(1, 64), tb>>>(Wb, WbTh, WbTl, CDIM, H_N);

  // low-rank gate paths
  gemm_fp16<<<gN1, 256, GSMEM>>>(xh, WfaTh, WfaTl, fa, MTOT, D_N, CDIM);
  convert_kernel<<<MTOT * D_N / 2048, 256>>>(fa, fah, MTOT * D_N);
  gemm_fp16<<<gBig, 256, GSMEM>>>(fah, WfbTh, WfbTl, gate, MTOT, CDIM, D_N);
  gemm_fp16<<<gN1, 256, GSMEM>>>(xh, WgaTh, WgaTl, ga, MTOT, D_N, CDIM);
  convert_kernel<<<MTOT * D_N / 2048, 256>>>(ga, gah, MTOT * D_N);
  gemm_fp16<<<gBig, 256, GSMEM>>>(gah, WgbTh, WgbTl, gog, MTOT, CDIM, D_N);
  // beta pre-activation (N=16, zfill + store guards)
  gemm_fp16<<<gN1, 256, GSMEM>>>(xh, WbTh, WbTl, beta, MTOT, H_N, CDIM);

  // fused conv + silu + l2norm + gate + beta
  conv_prep_kernel<<<MTOT * H_N, 128>>>(bq, bk, bv, conv_q_w, conv_k_w,
                                        conv_v_w, A_log, dt_bias, cq, ck, cv,
                                        gate, beta);

  // sequential scan (256 threads, 16-row groups)
  kda_scan_kernel<<<128, 256>>>(cq, ck, cv, gate, beta, oscan);

  // gated rmsnorm -> fp16
  gatenorm_kernel<<<MTOT * H_N, 128>>>(oscan, gog, o_norm_w, oh);

  // output projection
  gemm_fp16<<<gBig, 256, GSMEM>>>(oh, WoTh, WoTl, out, MTOT, CDIM, CDIM);
}